// round 3
// baseline (speedup 1.0000x reference)
#include <cuda_runtime.h>

#define Bn 4
#define Tn 2048
#define Cn 1024
#define HDn 64
#define NROWS (Bn*Tn)   // 8192
#define CHUNK 512
#define NCHUNK (Tn/CHUNK)   // 4

// Scratch (__device__ globals — allowed)
__device__ float g_q[NROWS*HDn];
__device__ float g_k[NROWS*HDn];
__device__ float g_v[NROWS*HDn];
__device__ float g_s[NROWS*Tn];              // scores z, then overwritten with e
__device__ float g_iden[NROWS];              // 1 / causal denominator
__device__ float g_part[NCHUNK*NROWS*HDn];   // split-s partial numerators (8MB)

// ---------------------------------------------------------------------------
// Kernel A: fused QKV projection.  [8192,1024] @ [1024, 64]x3
// ---------------------------------------------------------------------------
__global__ __launch_bounds__(256) void qkv_kernel(
    const float* __restrict__ x,
    const float* __restrict__ Wq,
    const float* __restrict__ Wk,
    const float* __restrict__ Wv)
{
    __shared__ float xs[32][68];    // x tile transposed [k][row]
    __shared__ float ws[32][196];   // W tile [k][Q|K|V cols]

    const int row0 = blockIdx.x * 64;
    const int tid  = threadIdx.x;
    const int tx   = tid & 15;
    const int ty   = tid >> 4;

    float acc[4][12];
    #pragma unroll
    for (int i = 0; i < 4; i++)
        #pragma unroll
        for (int j = 0; j < 12; j++) acc[i][j] = 0.f;

    for (int k0 = 0; k0 < Cn; k0 += 32) {
        __syncthreads();
        for (int i = tid; i < 64*8; i += 256) {
            int r = i >> 3, c4 = i & 7;
            float4 v = *(const float4*)&x[(size_t)(row0 + r)*Cn + k0 + c4*4];
            xs[c4*4+0][r] = v.x; xs[c4*4+1][r] = v.y;
            xs[c4*4+2][r] = v.z; xs[c4*4+3][r] = v.w;
        }
        for (int i = tid; i < 32*48; i += 256) {
            int kk = i / 48, j = i - kk*48;
            int which = j >> 4, c4 = j & 15;
            const float* W = (which == 0) ? Wq : ((which == 1) ? Wk : Wv);
            float4 v = *(const float4*)&W[(size_t)(k0+kk)*HDn + c4*4];
            *(float4*)&ws[kk][which*64 + c4*4] = v;
        }
        __syncthreads();
        #pragma unroll
        for (int kk = 0; kk < 32; kk++) {
            float a[4], bb[12];
            *(float4*)&a[0]  = *(const float4*)&xs[kk][ty*4];
            *(float4*)&bb[0] = *(const float4*)&ws[kk][tx*4];
            *(float4*)&bb[4] = *(const float4*)&ws[kk][64 + tx*4];
            *(float4*)&bb[8] = *(const float4*)&ws[kk][128 + tx*4];
            #pragma unroll
            for (int i = 0; i < 4; i++)
                #pragma unroll
                for (int j = 0; j < 12; j++)
                    acc[i][j] = fmaf(a[i], bb[j], acc[i][j]);
        }
    }
    #pragma unroll
    for (int i = 0; i < 4; i++) {
        size_t row = (size_t)(row0 + ty*4 + i);
        *(float4*)&g_q[row*HDn + tx*4] = *(float4*)&acc[i][0];
        *(float4*)&g_k[row*HDn + tx*4] = *(float4*)&acc[i][4];
        *(float4*)&g_v[row*HDn + tx*4] = *(float4*)&acc[i][8];
    }
}

// ---------------------------------------------------------------------------
// Kernel B1: scores z = 8 * Q K^T (full, unmasked)
// ---------------------------------------------------------------------------
__global__ __launch_bounds__(256) void scores_kernel()
{
    __shared__ float qT[32][132];
    __shared__ float kT[32][132];

    const int s0    = blockIdx.x * 128;
    const int row0  = blockIdx.y * 128;
    const int b     = row0 / Tn;
    const int krow0 = b * Tn + s0;
    const int tid   = threadIdx.x;
    const int tx    = tid & 15;
    const int ty    = tid >> 4;

    float acc[8][8];
    #pragma unroll
    for (int i = 0; i < 8; i++)
        #pragma unroll
        for (int j = 0; j < 8; j++) acc[i][j] = 0.f;

    for (int k0 = 0; k0 < HDn; k0 += 32) {
        __syncthreads();
        for (int i = tid; i < 128*8; i += 256) {
            int r = i >> 3, c4 = i & 7;
            float4 v = *(const float4*)&g_q[(size_t)(row0 + r)*HDn + k0 + c4*4];
            qT[c4*4+0][r] = v.x; qT[c4*4+1][r] = v.y;
            qT[c4*4+2][r] = v.z; qT[c4*4+3][r] = v.w;
            float4 w = *(const float4*)&g_k[(size_t)(krow0 + r)*HDn + k0 + c4*4];
            kT[c4*4+0][r] = w.x; kT[c4*4+1][r] = w.y;
            kT[c4*4+2][r] = w.z; kT[c4*4+3][r] = w.w;
        }
        __syncthreads();
        #pragma unroll
        for (int kk = 0; kk < 32; kk++) {
            float a[8], bb[8];
            *(float4*)&a[0]  = *(const float4*)&qT[kk][ty*4];
            *(float4*)&a[4]  = *(const float4*)&qT[kk][64 + ty*4];
            *(float4*)&bb[0] = *(const float4*)&kT[kk][tx*4];
            *(float4*)&bb[4] = *(const float4*)&kT[kk][64 + tx*4];
            #pragma unroll
            for (int i = 0; i < 8; i++)
                #pragma unroll
                for (int j = 0; j < 8; j++)
                    acc[i][j] = fmaf(a[i], bb[j], acc[i][j]);
        }
    }
    #pragma unroll
    for (int i = 0; i < 8; i++) {
        int row = row0 + ((i >> 2) ? 64 : 0) + ty*4 + (i & 3);
        float* dst = &g_s[(size_t)row*Tn + s0];
        float4 o0 = make_float4(acc[i][0]*8.f, acc[i][1]*8.f, acc[i][2]*8.f, acc[i][3]*8.f);
        float4 o1 = make_float4(acc[i][4]*8.f, acc[i][5]*8.f, acc[i][6]*8.f, acc[i][7]*8.f);
        *(float4*)&dst[tx*4]      = o0;
        *(float4*)&dst[64 + tx*4] = o1;
    }
}

// ---------------------------------------------------------------------------
// Kernel B2: per-row: m, Z over full row; then overwrite row with
//            e = exp(exp(z-m)/Z) for s<=t, 0 for s>t; write 1/sum(e).
// One warp per row; entire row lives in 64 registers.
// ---------------------------------------------------------------------------
__global__ __launch_bounds__(256) void stats_kernel()
{
    const int row  = blockIdx.x * 8 + (threadIdx.x >> 5);
    const int lane = threadIdx.x & 31;
    const int t    = row & (Tn - 1);
    float* zr = &g_s[(size_t)row * Tn];

    float4 v[16];
    #pragma unroll
    for (int w = 0; w < 16; w++)
        v[w] = *(const float4*)&zr[w*128 + lane*4];

    float m = -1e30f;
    #pragma unroll
    for (int w = 0; w < 16; w++)
        m = fmaxf(m, fmaxf(fmaxf(v[w].x, v[w].y), fmaxf(v[w].z, v[w].w)));
    #pragma unroll
    for (int off = 16; off > 0; off >>= 1)
        m = fmaxf(m, __shfl_xor_sync(0xffffffffu, m, off));

    // p = exp(z - m), Z = sum(p)  (overwrite v with p)
    float Z = 0.f;
    #pragma unroll
    for (int w = 0; w < 16; w++) {
        v[w].x = __expf(v[w].x - m); v[w].y = __expf(v[w].y - m);
        v[w].z = __expf(v[w].z - m); v[w].w = __expf(v[w].w - m);
        Z += v[w].x + v[w].y + v[w].z + v[w].w;
    }
    #pragma unroll
    for (int off = 16; off > 0; off >>= 1)
        Z += __shfl_xor_sync(0xffffffffu, Z, off);
    const float iz = 1.f / Z;

    // e = exp(p/Z) causal, else 0; write back; den = sum(e)
    float den = 0.f;
    #pragma unroll
    for (int w = 0; w < 16; w++) {
        const int sbase = w*128 + lane*4;
        float4 e;
        e.x = (sbase + 0 <= t) ? __expf(v[w].x * iz) : 0.f;
        e.y = (sbase + 1 <= t) ? __expf(v[w].y * iz) : 0.f;
        e.z = (sbase + 2 <= t) ? __expf(v[w].z * iz) : 0.f;
        e.w = (sbase + 3 <= t) ? __expf(v[w].w * iz) : 0.f;
        den += e.x + e.y + e.z + e.w;
        *(float4*)&zr[sbase] = e;
    }
    #pragma unroll
    for (int off = 16; off > 0; off >>= 1)
        den += __shfl_xor_sync(0xffffffffu, den, off);

    if (lane == 0) g_iden[row] = 1.f / den;
}

// ---------------------------------------------------------------------------
// Kernel B3: split-s partial GEMM  part[c] = e[:, c*512:(c+1)*512] @ V-chunk
// grid (chunk=4, rowblock=64); CTA tile 128 rows x 64 d; thread tile 8x4.
// ---------------------------------------------------------------------------
__global__ __launch_bounds__(256) void outp_kernel()
{
    const int chunk = blockIdx.x;
    const int row0  = blockIdx.y * 128;
    const int b     = row0 / Tn;
    const int t0    = row0 - b * Tn;
    const int sbeg  = chunk * CHUNK;
    if (sbeg > t0 + 127) return;                 // fully above diagonal
    const int send  = min(sbeg + CHUNK, t0 + 128);  // multiple of 32
    const int nk    = (send - sbeg) >> 5;

    __shared__ float eT[32][132];    // [s][row]
    __shared__ float vs[32][68];     // [s][d]

    const int tid = threadIdx.x;
    const int tx  = tid & 15;        // 4 d cols each
    const int ty  = tid >> 4;        // 8 rows each

    float acc[8][4];
    #pragma unroll
    for (int i = 0; i < 8; i++)
        #pragma unroll
        for (int j = 0; j < 4; j++) acc[i][j] = 0.f;

    for (int kt = 0; kt < nk; kt++) {
        const int s0 = sbeg + kt*32;
        __syncthreads();
        // e tile: 128 rows x 32 s, transposed into smem
        for (int i = tid; i < 128*8; i += 256) {
            int r = i >> 3, c4 = i & 7;
            float4 e4 = *(const float4*)&g_s[(size_t)(row0 + r)*Tn + s0 + c4*4];
            eT[c4*4+0][r] = e4.x; eT[c4*4+1][r] = e4.y;
            eT[c4*4+2][r] = e4.z; eT[c4*4+3][r] = e4.w;
        }
        // V tile: 32 s x 64 d
        for (int i = tid; i < 32*16; i += 256) {
            int s = i >> 4, d4 = i & 15;
            *(float4*)&vs[s][d4*4] =
                *(const float4*)&g_v[(size_t)(b*Tn + s0 + s)*HDn + d4*4];
        }
        __syncthreads();
        #pragma unroll
        for (int kk = 0; kk < 32; kk++) {
            float a[8], bb[4];
            *(float4*)&a[0]  = *(const float4*)&eT[kk][ty*8];
            *(float4*)&a[4]  = *(const float4*)&eT[kk][ty*8 + 4];
            *(float4*)&bb[0] = *(const float4*)&vs[kk][tx*4];
            #pragma unroll
            for (int i = 0; i < 8; i++)
                #pragma unroll
                for (int j = 0; j < 4; j++)
                    acc[i][j] = fmaf(a[i], bb[j], acc[i][j]);
        }
    }

    float* dst = &g_part[((size_t)chunk*NROWS + row0)*HDn];
    #pragma unroll
    for (int i = 0; i < 8; i++) {
        int r = ty*8 + i;
        *(float4*)&dst[(size_t)r*HDn + tx*4] = *(float4*)&acc[i][0];
    }
}

// ---------------------------------------------------------------------------
// Kernel B4: finalize — sum valid chunk partials, scale by 1/den.
// One thread per float4 of output.
// ---------------------------------------------------------------------------
__global__ __launch_bounds__(256) void fin_kernel(float* __restrict__ out)
{
    const int idx = blockIdx.x * 256 + threadIdx.x;   // 131072 total
    const int row = idx >> 4;
    const int d4  = (idx & 15) * 4;
    const int t0r = row & (Tn - 1);
    const int nch = ((t0r | 127) >> 9) + 1;           // chunks that actually ran

    float4 s = make_float4(0.f, 0.f, 0.f, 0.f);
    for (int c = 0; c < nch; c++) {
        float4 p = *(const float4*)&g_part[((size_t)c*NROWS + row)*HDn + d4];
        s.x += p.x; s.y += p.y; s.z += p.z; s.w += p.w;
    }
    const float inv = g_iden[row];
    s.x *= inv; s.y *= inv; s.z *= inv; s.w *= inv;
    *(float4*)&out[(size_t)row*HDn + d4] = s;
}

// ---------------------------------------------------------------------------
extern "C" void kernel_launch(void* const* d_in, const int* in_sizes, int n_in,
                              void* d_out, int out_size)
{
    const float* x  = (const float*)d_in[0];
    const float* Wq = (const float*)d_in[1];
    const float* Wk = (const float*)d_in[2];
    const float* Wv = (const float*)d_in[3];
    float* out = (float*)d_out;

    qkv_kernel<<<NROWS/64, 256>>>(x, Wq, Wk, Wv);
    scores_kernel<<<dim3(Tn/128, NROWS/128), 256>>>();
    stats_kernel<<<NROWS/8, 256>>>();
    outp_kernel<<<dim3(NCHUNK, NROWS/128), 256>>>();
    fin_kernel<<<(NROWS*HDn/4)/256, 256>>>(out);
}

// round 4
// speedup vs baseline: 1.4835x; 1.4835x over previous
#include <cuda_runtime.h>

#define Bn 4
#define Tn 2048
#define Cn 1024
#define HDn 64
#define NROWS (Bn*Tn)       // 8192
#define CHUNK 256
#define NCHUNK (Tn/CHUNK)   // 8

typedef unsigned long long ull;

// Scratch (__device__ globals — allowed)
__device__ float g_q[NROWS*HDn];
__device__ float g_k[NROWS*HDn];
__device__ float g_v[NROWS*HDn];
__device__ float g_s[NROWS*Tn];              // raw scores z (unscaled)
__device__ float g_m8[NROWS];                // 8 * rowmax(z)
__device__ float g_iz[NROWS];                // 1 / Z (first softmax)
__device__ float g_iden[NROWS];              // 1 / causal denominator
__device__ float g_part[NCHUNK*NROWS*HDn];   // split-s partial numerators

// ---- f32x2 helpers -------------------------------------------------------
__device__ __forceinline__ ull pack2(float x, float y) {
    ull r;
    asm("mov.b64 %0, {%1, %2};" : "=l"(r)
        : "r"(__float_as_uint(x)), "r"(__float_as_uint(y)));
    return r;
}
__device__ __forceinline__ ull bcast2(float x) { return pack2(x, x); }
__device__ __forceinline__ void fma2(ull& c, ull a, ull b) {
    asm("fma.rn.f32x2 %0, %1, %2, %0;" : "+l"(c) : "l"(a), "l"(b));
}
__device__ __forceinline__ float2 unpack2(ull v) {
    unsigned lo, hi;
    asm("mov.b64 {%0, %1}, %2;" : "=r"(lo), "=r"(hi) : "l"(v));
    return make_float2(__uint_as_float(lo), __uint_as_float(hi));
}

// ---------------------------------------------------------------------------
// Kernel A: QKV projection. grid (2 col-halves, 64 row-blocks of 128).
// CTA tile 128 rows x 96 cols over K=1024; 128 threads; thread tile 16x6
// (row-pair packed accumulators, f32x2 FMA).
// ---------------------------------------------------------------------------
__global__ __launch_bounds__(128) void qkv_kernel(
    const float* __restrict__ x,
    const float* __restrict__ Wq,
    const float* __restrict__ Wk,
    const float* __restrict__ Wv)
{
    __shared__ float xs[32][132];   // x tile transposed [k][row]
    __shared__ float ws[32][100];   // W tile [k][96 cols of this half]

    const int ch   = blockIdx.x;          // 0..1
    const int row0 = blockIdx.y * 128;
    const int tid  = threadIdx.x;
    const int ty   = tid >> 4;            // 0..7  -> rows ty*16 .. +15
    const int tx   = tid & 15;            // 0..15 -> cols tx*6 .. +5

    ull c2[8][6];
    #pragma unroll
    for (int i = 0; i < 8; i++)
        #pragma unroll
        for (int j = 0; j < 6; j++) c2[i][j] = 0ULL;

    for (int k0 = 0; k0 < Cn; k0 += 32) {
        __syncthreads();
        // x tile: 128 rows x 32 k, transposed
        for (int i = tid; i < 128*8; i += 128) {
            int r = i >> 3, q = i & 7;
            float4 v = *(const float4*)&x[(size_t)(row0 + r)*Cn + k0 + q*4];
            xs[q*4+0][r] = v.x; xs[q*4+1][r] = v.y;
            xs[q*4+2][r] = v.z; xs[q*4+3][r] = v.w;
        }
        // W tile: 32 k x 96 cols (this half of the 192-wide QKV concat)
        for (int i = tid; i < 32*24; i += 128) {
            int kk = i / 24, c4 = i - kk*24;
            int gc = ch*96 + c4*4;
            const float* W = (gc < 64) ? Wq : ((gc < 128) ? Wk : Wv);
            float4 v = *(const float4*)&W[(size_t)(k0+kk)*HDn + (gc & 63)];
            *(float4*)&ws[kk][c4*4] = v;
        }
        __syncthreads();
        #pragma unroll 8
        for (int kk = 0; kk < 32; kk++) {
            ull a2[8];
            #pragma unroll
            for (int q = 0; q < 8; q++)
                a2[q] = *(const ull*)&xs[kk][ty*16 + 2*q];
            ull b2[6];
            #pragma unroll
            for (int j = 0; j < 6; j++)
                b2[j] = bcast2(ws[kk][tx*6 + j]);
            #pragma unroll
            for (int q = 0; q < 8; q++)
                #pragma unroll
                for (int j = 0; j < 6; j++)
                    fma2(c2[q][j], a2[q], b2[j]);
        }
    }
    // epilogue: scatter to g_q / g_k / g_v
    #pragma unroll
    for (int q = 0; q < 8; q++) {
        #pragma unroll
        for (int j = 0; j < 6; j++) {
            float2 v = unpack2(c2[q][j]);
            int gc = ch*96 + tx*6 + j;
            float* dst = (gc < 64) ? g_q : ((gc < 128) ? g_k : g_v);
            int dcol = gc & 63;
            size_t r = (size_t)(row0 + ty*16 + 2*q);
            dst[r*HDn + dcol]       = v.x;
            dst[(r+1)*HDn + dcol]   = v.y;
        }
    }
}

// ---------------------------------------------------------------------------
// Kernel B1: raw scores z = Q K^T (x8 scaling deferred to the exp FMA).
// grid (16 s-blocks, 64 row-blocks); CTA 128x128; 256 thr; thread tile 8x8
// row-pair packed; b cols interleaved lo/hi halves (full-bank LDS.128).
// ---------------------------------------------------------------------------
__global__ __launch_bounds__(256) void scores_kernel()
{
    __shared__ float qT[32][132];
    __shared__ float kT[32][132];

    const int s0    = blockIdx.x * 128;
    const int row0  = blockIdx.y * 128;
    const int b     = row0 >> 11;
    const int krow0 = b * Tn + s0;
    const int tid   = threadIdx.x;
    const int ty    = tid >> 4;     // 0..15 -> rows ty*8..+7
    const int tx    = tid & 15;     // cols tx*4..+3 and 64+tx*4..+3

    ull c2[4][8];
    #pragma unroll
    for (int i = 0; i < 4; i++)
        #pragma unroll
        for (int j = 0; j < 8; j++) c2[i][j] = 0ULL;

    for (int k0 = 0; k0 < HDn; k0 += 32) {
        __syncthreads();
        for (int i = tid; i < 128*8; i += 256) {
            int r = i >> 3, c4 = i & 7;
            float4 v = *(const float4*)&g_q[(size_t)(row0 + r)*HDn + k0 + c4*4];
            qT[c4*4+0][r] = v.x; qT[c4*4+1][r] = v.y;
            qT[c4*4+2][r] = v.z; qT[c4*4+3][r] = v.w;
            float4 w = *(const float4*)&g_k[(size_t)(krow0 + r)*HDn + k0 + c4*4];
            kT[c4*4+0][r] = w.x; kT[c4*4+1][r] = w.y;
            kT[c4*4+2][r] = w.z; kT[c4*4+3][r] = w.w;
        }
        __syncthreads();
        #pragma unroll 8
        for (int kk = 0; kk < 32; kk++) {
            ull a2[4];
            #pragma unroll
            for (int i = 0; i < 4; i++)
                a2[i] = *(const ull*)&qT[kk][ty*8 + 2*i];
            float4 bv0 = *(const float4*)&kT[kk][tx*4];
            float4 bv1 = *(const float4*)&kT[kk][64 + tx*4];
            ull b2[8] = { bcast2(bv0.x), bcast2(bv0.y), bcast2(bv0.z), bcast2(bv0.w),
                          bcast2(bv1.x), bcast2(bv1.y), bcast2(bv1.z), bcast2(bv1.w) };
            #pragma unroll
            for (int i = 0; i < 4; i++)
                #pragma unroll
                for (int j = 0; j < 8; j++)
                    fma2(c2[i][j], a2[i], b2[j]);
        }
    }
    // epilogue: store raw z
    #pragma unroll
    for (int i = 0; i < 4; i++) {
        float2 p[8];
        #pragma unroll
        for (int j = 0; j < 8; j++) p[j] = unpack2(c2[i][j]);
        #pragma unroll
        for (int h = 0; h < 2; h++) {
            int row = row0 + ty*8 + 2*i + h;
            float* dst = &g_s[(size_t)row*Tn + s0];
            float4 A, B;
            A.x = h ? p[0].y : p[0].x;  A.y = h ? p[1].y : p[1].x;
            A.z = h ? p[2].y : p[2].x;  A.w = h ? p[3].y : p[3].x;
            B.x = h ? p[4].y : p[4].x;  B.y = h ? p[5].y : p[5].x;
            B.z = h ? p[6].y : p[6].x;  B.w = h ? p[7].y : p[7].x;
            *(float4*)&dst[tx*4]      = A;
            *(float4*)&dst[64 + tx*4] = B;
        }
    }
}

// ---------------------------------------------------------------------------
// Kernel B2: per-row stats only (no write-back): m8 = 8*max, iz = 1/Z,
// iden = 1/sum_{s<=t} exp(exp(8(z-m))/Z). One warp per row, row in registers.
// ---------------------------------------------------------------------------
__global__ __launch_bounds__(256) void stats_kernel()
{
    const int row  = blockIdx.x * 8 + (threadIdx.x >> 5);
    const int lane = threadIdx.x & 31;
    const int t    = row & (Tn - 1);
    const float* zr = &g_s[(size_t)row * Tn];

    float4 v[16];
    #pragma unroll
    for (int w = 0; w < 16; w++)
        v[w] = *(const float4*)&zr[w*128 + lane*4];

    float m = -1e30f;
    #pragma unroll
    for (int w = 0; w < 16; w++)
        m = fmaxf(m, fmaxf(fmaxf(v[w].x, v[w].y), fmaxf(v[w].z, v[w].w)));
    #pragma unroll
    for (int off = 16; off > 0; off >>= 1)
        m = fmaxf(m, __shfl_xor_sync(0xffffffffu, m, off));
    const float m8 = 8.f * m;

    float Z = 0.f;
    #pragma unroll
    for (int w = 0; w < 16; w++) {
        v[w].x = __expf(fmaf(v[w].x, 8.f, -m8));
        v[w].y = __expf(fmaf(v[w].y, 8.f, -m8));
        v[w].z = __expf(fmaf(v[w].z, 8.f, -m8));
        v[w].w = __expf(fmaf(v[w].w, 8.f, -m8));
        Z += v[w].x + v[w].y + v[w].z + v[w].w;
    }
    #pragma unroll
    for (int off = 16; off > 0; off >>= 1)
        Z += __shfl_xor_sync(0xffffffffu, Z, off);
    const float iz = 1.f / Z;

    float den = 0.f;
    #pragma unroll
    for (int w = 0; w < 16; w++) {
        const int sbase = w*128 + lane*4;
        den += (sbase + 0 <= t) ? __expf(v[w].x * iz) : 0.f;
        den += (sbase + 1 <= t) ? __expf(v[w].y * iz) : 0.f;
        den += (sbase + 2 <= t) ? __expf(v[w].z * iz) : 0.f;
        den += (sbase + 3 <= t) ? __expf(v[w].w * iz) : 0.f;
    }
    #pragma unroll
    for (int off = 16; off > 0; off >>= 1)
        den += __shfl_xor_sync(0xffffffffu, den, off);

    if (lane == 0) {
        g_m8[row] = m8; g_iz[row] = iz; g_iden[row] = 1.f / den;
    }
}

// ---------------------------------------------------------------------------
// Kernel B3: split-s partial numerators with on-the-fly e generation.
// grid (8 chunks of 256, 64 row-blocks of 128); 128 threads.
// Thread lr==tid owns row lr for e generation (contiguous 128B z reads).
// GEMM: thread tile 8x8 row-pair packed (ty=tid>>3 rows, tx=tid&7 cols).
// ---------------------------------------------------------------------------
__global__ __launch_bounds__(128) void outp_kernel()
{
    const int chunk = blockIdx.x;
    const int row0  = blockIdx.y * 128;
    const int b     = row0 >> 11;
    const int t0    = row0 & (Tn - 1);
    const int sbeg  = chunk * CHUNK;
    if (sbeg > t0 + 127) return;
    const int send  = min(sbeg + CHUNK, t0 + 128);
    const int nk    = (send - sbeg) >> 5;

    __shared__ float eT[32][132];    // [s][row]
    __shared__ float vs[32][68];     // [s][d]

    const int tid = threadIdx.x;
    const int ty  = tid >> 3;        // 0..15 -> rows ty*8..+7
    const int tx  = tid & 7;         // cols tx*4..+3 and 32+tx*4..+3
    const int lr  = tid;             // row owned for e-gen
    const int t_my = t0 + lr;

    const float m8 = g_m8[row0 + lr];
    const float iz = g_iz[row0 + lr];
    const float* zrow = &g_s[(size_t)(row0 + lr)*Tn];

    ull c2[4][8];
    #pragma unroll
    for (int i = 0; i < 4; i++)
        #pragma unroll
        for (int j = 0; j < 8; j++) c2[i][j] = 0ULL;

    for (int kt = 0; kt < nk; kt++) {
        const int s0 = sbeg + kt*32;
        __syncthreads();
        // V tile 32 x 64
        for (int i = tid; i < 512; i += 128) {
            int s = i >> 4, d4 = i & 15;
            *(float4*)&vs[s][d4*4] =
                *(const float4*)&g_v[(size_t)(b*Tn + s0 + s)*HDn + d4*4];
        }
        // e row: thread lr loads its 32 z's (contiguous 128B), exps, transposed STS
        #pragma unroll
        for (int q = 0; q < 8; q++) {
            float4 z = *(const float4*)&zrow[s0 + q*4];
            float zz[4] = {z.x, z.y, z.z, z.w};
            #pragma unroll
            for (int c = 0; c < 4; c++) {
                int s = s0 + q*4 + c;
                float e = 0.f;
                if (s <= t_my)
                    e = __expf(__expf(fmaf(zz[c], 8.f, -m8)) * iz);
                eT[q*4 + c][lr] = e;
            }
        }
        __syncthreads();
        #pragma unroll 8
        for (int kk = 0; kk < 32; kk++) {
            ull a2[4];
            #pragma unroll
            for (int i = 0; i < 4; i++)
                a2[i] = *(const ull*)&eT[kk][ty*8 + 2*i];
            float4 bv0 = *(const float4*)&vs[kk][tx*4];
            float4 bv1 = *(const float4*)&vs[kk][32 + tx*4];
            ull b2[8] = { bcast2(bv0.x), bcast2(bv0.y), bcast2(bv0.z), bcast2(bv0.w),
                          bcast2(bv1.x), bcast2(bv1.y), bcast2(bv1.z), bcast2(bv1.w) };
            #pragma unroll
            for (int i = 0; i < 4; i++)
                #pragma unroll
                for (int j = 0; j < 8; j++)
                    fma2(c2[i][j], a2[i], b2[j]);
        }
    }

    float* dst = &g_part[((size_t)chunk*NROWS + row0)*HDn];
    #pragma unroll
    for (int i = 0; i < 4; i++) {
        float2 p[8];
        #pragma unroll
        for (int j = 0; j < 8; j++) p[j] = unpack2(c2[i][j]);
        #pragma unroll
        for (int h = 0; h < 2; h++) {
            int r = ty*8 + 2*i + h;
            float4 A, B;
            A.x = h ? p[0].y : p[0].x;  A.y = h ? p[1].y : p[1].x;
            A.z = h ? p[2].y : p[2].x;  A.w = h ? p[3].y : p[3].x;
            B.x = h ? p[4].y : p[4].x;  B.y = h ? p[5].y : p[5].x;
            B.z = h ? p[6].y : p[6].x;  B.w = h ? p[7].y : p[7].x;
            *(float4*)&dst[(size_t)r*HDn + tx*4]      = A;
            *(float4*)&dst[(size_t)r*HDn + 32 + tx*4] = B;
        }
    }
}

// ---------------------------------------------------------------------------
// Kernel B4: finalize — sum valid chunk partials, scale by 1/den.
// ---------------------------------------------------------------------------
__global__ __launch_bounds__(256) void fin_kernel(float* __restrict__ out)
{
    const int idx = blockIdx.x * 256 + threadIdx.x;   // 131072 total
    const int row = idx >> 4;
    const int d4  = (idx & 15) * 4;
    const int nch = (((row & (Tn-1)) | 127) / CHUNK) + 1;

    float4 s = make_float4(0.f, 0.f, 0.f, 0.f);
    for (int c = 0; c < nch; c++) {
        float4 p = *(const float4*)&g_part[((size_t)c*NROWS + row)*HDn + d4];
        s.x += p.x; s.y += p.y; s.z += p.z; s.w += p.w;
    }
    const float inv = g_iden[row];
    s.x *= inv; s.y *= inv; s.z *= inv; s.w *= inv;
    *(float4*)&out[(size_t)row*HDn + d4] = s;
}

// ---------------------------------------------------------------------------
extern "C" void kernel_launch(void* const* d_in, const int* in_sizes, int n_in,
                              void* d_out, int out_size)
{
    const float* x  = (const float*)d_in[0];
    const float* Wq = (const float*)d_in[1];
    const float* Wk = (const float*)d_in[2];
    const float* Wv = (const float*)d_in[3];
    float* out = (float*)d_out;

    qkv_kernel<<<dim3(2, NROWS/128), 128>>>(x, Wq, Wk, Wv);
    scores_kernel<<<dim3(Tn/128, NROWS/128), 256>>>();
    stats_kernel<<<NROWS/8, 256>>>();
    outp_kernel<<<dim3(NCHUNK, NROWS/128), 128>>>();
    fin_kernel<<<(NROWS*HDn/4)/256, 256>>>(out);
}

// round 6
// speedup vs baseline: 1.5892x; 1.0713x over previous
#include <cuda_runtime.h>
#include <cuda_bf16.h>
#include <cstdint>

#define Bn 4
#define Tn 2048
#define Cn 1024
#define HDn 64
#define NROWS (Bn*Tn)       // 8192
#define CHUNK 256
#define NCHUNK (Tn/CHUNK)   // 8

typedef unsigned long long ull;

// Scratch (__device__ globals — allowed)
__device__ __nv_bfloat16 g_qhi[NROWS*HDn];
__device__ __nv_bfloat16 g_qlo[NROWS*HDn];
__device__ __nv_bfloat16 g_khi[NROWS*HDn];
__device__ __nv_bfloat16 g_klo[NROWS*HDn];
__device__ float g_v[NROWS*HDn];
__device__ float g_s[NROWS*Tn];              // raw scores z (unscaled)
__device__ float g_m8[NROWS];                // 8 * rowmax(z)
__device__ float g_iz[NROWS];                // 1 / Z (first softmax)
__device__ float g_iden[NROWS];              // 1 / causal denominator
__device__ float g_part[NCHUNK*NROWS*HDn];   // split-s partial numerators

// ---- f32x2 helpers -------------------------------------------------------
__device__ __forceinline__ ull pack2(float x, float y) {
    ull r;
    asm("mov.b64 %0, {%1, %2};" : "=l"(r)
        : "r"(__float_as_uint(x)), "r"(__float_as_uint(y)));
    return r;
}
__device__ __forceinline__ ull bcast2(float x) { return pack2(x, x); }
__device__ __forceinline__ void fma2(ull& c, ull a, ull b) {
    asm("fma.rn.f32x2 %0, %1, %2, %0;" : "+l"(c) : "l"(a), "l"(b));
}
__device__ __forceinline__ float2 unpack2(ull v) {
    unsigned lo, hi;
    asm("mov.b64 {%0, %1}, %2;" : "=r"(lo), "=r"(hi) : "l"(v));
    return make_float2(__uint_as_float(lo), __uint_as_float(hi));
}

// ---- mma.sync helpers ----------------------------------------------------
__device__ __forceinline__ uint32_t smem_u32(const void* p) {
    uint32_t a;
    asm("{ .reg .u64 t; cvta.to.shared.u64 t, %1; cvt.u32.u64 %0, t; }"
        : "=r"(a) : "l"(p));
    return a;
}
#define SW128(o) ((o) ^ (((o) >> 3) & 0x70))

__device__ __forceinline__ void ldsm4(uint32_t* r, uint32_t addr) {
    asm volatile("ldmatrix.sync.aligned.m8n8.x4.shared.b16 {%0,%1,%2,%3}, [%4];"
                 : "=r"(r[0]), "=r"(r[1]), "=r"(r[2]), "=r"(r[3]) : "r"(addr));
}
__device__ __forceinline__ void mma16816(float* c, const uint32_t* a,
                                         uint32_t b0, uint32_t b1) {
    asm volatile("mma.sync.aligned.m16n8k16.row.col.f32.bf16.bf16.f32 "
                 "{%0,%1,%2,%3}, {%4,%5,%6,%7}, {%8,%9}, {%0,%1,%2,%3};"
                 : "+f"(c[0]), "+f"(c[1]), "+f"(c[2]), "+f"(c[3])
                 : "r"(a[0]), "r"(a[1]), "r"(a[2]), "r"(a[3]), "r"(b0), "r"(b1));
}

// ---------------------------------------------------------------------------
// Kernel A: QKV projection (f32x2 SIMT). Emits Q,K as bf16 hi/lo; V fp32.
// ---------------------------------------------------------------------------
__global__ __launch_bounds__(128) void qkv_kernel(
    const float* __restrict__ x,
    const float* __restrict__ Wq,
    const float* __restrict__ Wk,
    const float* __restrict__ Wv)
{
    __shared__ float xs[32][132];
    __shared__ float ws[32][100];

    const int ch   = blockIdx.x;
    const int row0 = blockIdx.y * 128;
    const int tid  = threadIdx.x;
    const int ty   = tid >> 4;
    const int tx   = tid & 15;

    ull c2[8][6];
    #pragma unroll
    for (int i = 0; i < 8; i++)
        #pragma unroll
        for (int j = 0; j < 6; j++) c2[i][j] = 0ULL;

    for (int k0 = 0; k0 < Cn; k0 += 32) {
        __syncthreads();
        for (int i = tid; i < 128*8; i += 128) {
            int r = i >> 3, q = i & 7;
            float4 v = *(const float4*)&x[(size_t)(row0 + r)*Cn + k0 + q*4];
            xs[q*4+0][r] = v.x; xs[q*4+1][r] = v.y;
            xs[q*4+2][r] = v.z; xs[q*4+3][r] = v.w;
        }
        for (int i = tid; i < 32*24; i += 128) {
            int kk = i / 24, c4 = i - kk*24;
            int gc = ch*96 + c4*4;
            const float* W = (gc < 64) ? Wq : ((gc < 128) ? Wk : Wv);
            float4 v = *(const float4*)&W[(size_t)(k0+kk)*HDn + (gc & 63)];
            *(float4*)&ws[kk][c4*4] = v;
        }
        __syncthreads();
        #pragma unroll 8
        for (int kk = 0; kk < 32; kk++) {
            ull a2[8];
            #pragma unroll
            for (int q = 0; q < 8; q++)
                a2[q] = *(const ull*)&xs[kk][ty*16 + 2*q];
            ull b2[6];
            #pragma unroll
            for (int j = 0; j < 6; j++)
                b2[j] = bcast2(ws[kk][tx*6 + j]);
            #pragma unroll
            for (int q = 0; q < 8; q++)
                #pragma unroll
                for (int j = 0; j < 6; j++)
                    fma2(c2[q][j], a2[q], b2[j]);
        }
    }
    #pragma unroll
    for (int q = 0; q < 8; q++) {
        #pragma unroll
        for (int j = 0; j < 6; j++) {
            float2 v = unpack2(c2[q][j]);
            int gc = ch*96 + tx*6 + j;
            int dcol = gc & 63;
            size_t r = (size_t)(row0 + ty*16 + 2*q);
            float vv[2] = {v.x, v.y};
            #pragma unroll
            for (int h = 0; h < 2; h++) {
                size_t o = (r + h)*HDn + dcol;
                if (gc < 128) {
                    __nv_bfloat16 hi = __float2bfloat16(vv[h]);
                    __nv_bfloat16 lo = __float2bfloat16(vv[h] - __bfloat162float(hi));
                    if (gc < 64) { g_qhi[o] = hi; g_qlo[o] = lo; }
                    else         { g_khi[o] = hi; g_klo[o] = lo; }
                } else {
                    g_v[o] = vv[h];
                }
            }
        }
    }
}

// ---------------------------------------------------------------------------
// Kernel B1: scores via warp-level mma.sync (bf16 split, fp32 accum).
// CTA: 128 rows x 128 keys; 8 warps (4 m x 2 n), warp tile 32x64.
// SMEM: Qhi/Qlo/Khi/Klo 128x64 bf16, SW128 swizzle (128B rows).
// z = Qhi Khi^T + Qhi Klo^T + Qlo Khi^T.
// ---------------------------------------------------------------------------
#define SC_QHI     0
#define SC_QLO     (SC_QHI + 16384)
#define SC_KHI     (SC_QLO + 16384)
#define SC_KLO     (SC_KHI + 16384)
#define SC_SMEM    (SC_KLO + 16384)

__device__ __forceinline__ void sc_load_tile(char* smem, int dstoff,
    const __nv_bfloat16* __restrict__ src, int row0, int tid)
{
    #pragma unroll
    for (int c = tid; c < 1024; c += 256) {
        int r = c >> 3, o = (c & 7) * 16;
        uint4 v = *(const uint4*)((const char*)(src + (size_t)(row0 + r)*HDn) + o);
        *(uint4*)(smem + dstoff + SW128(r*128 + o)) = v;
    }
}

__global__ __launch_bounds__(256) void scores_mma()
{
    extern __shared__ char smem[];
    const uint32_t sb = smem_u32(smem);
    const int tid  = threadIdx.x;
    const int wid  = tid >> 5;
    const int lane = tid & 31;

    const int s0    = blockIdx.x * 128;
    const int row0  = blockIdx.y * 128;
    const int b     = row0 >> 11;
    const int krow0 = b * Tn + s0;

    sc_load_tile(smem, SC_QHI, g_qhi, row0, tid);
    sc_load_tile(smem, SC_QLO, g_qlo, row0, tid);
    sc_load_tile(smem, SC_KHI, g_khi, krow0, tid);
    sc_load_tile(smem, SC_KLO, g_klo, krow0, tid);
    __syncthreads();

    const int wm = wid & 3;        // m block: rows wm*32 .. +31
    const int wn = wid >> 2;       // n block: keys wn*64 .. +63

    float c[2][8][4];
    #pragma unroll
    for (int mt = 0; mt < 2; mt++)
        #pragma unroll
        for (int nt = 0; nt < 8; nt++)
            #pragma unroll
            for (int q = 0; q < 4; q++) c[mt][nt][q] = 0.f;

    // per-lane ldmatrix row/col pattern
    const int lrow = lane & 15;
    const int lcol = (lane >> 4) * 16;   // bytes (8 halves)

    #pragma unroll
    for (int k = 0; k < 4; k++) {
        const int kb = k * 32;           // byte offset of k0 (16 halves)
        uint32_t ahi[2][4], alo[2][4];
        #pragma unroll
        for (int mt = 0; mt < 2; mt++) {
            int r = wm*32 + mt*16 + lrow;
            ldsm4(ahi[mt], sb + SC_QHI + SW128(r*128 + kb + lcol));
            ldsm4(alo[mt], sb + SC_QLO + SW128(r*128 + kb + lcol));
        }
        #pragma unroll
        for (int nt2 = 0; nt2 < 4; nt2++) {
            int r = wn*64 + nt2*16 + lrow;
            uint32_t bh[4], bl[4];
            ldsm4(bh, sb + SC_KHI + SW128(r*128 + kb + lcol));
            ldsm4(bl, sb + SC_KLO + SW128(r*128 + kb + lcol));
            #pragma unroll
            for (int mt = 0; mt < 2; mt++) {
                float* c0 = c[mt][nt2*2+0];
                float* c1 = c[mt][nt2*2+1];
                mma16816(c0, ahi[mt], bh[0], bh[2]);
                mma16816(c1, ahi[mt], bh[1], bh[3]);
                mma16816(c0, ahi[mt], bl[0], bl[2]);
                mma16816(c1, ahi[mt], bl[1], bl[3]);
                mma16816(c0, alo[mt], bh[0], bh[2]);
                mma16816(c1, alo[mt], bh[1], bh[3]);
            }
        }
    }

    // epilogue: c fragment -> g_s.  row = lane/4 (+8), col = (lane%3)*2 pairs
    #pragma unroll
    for (int mt = 0; mt < 2; mt++) {
        #pragma unroll
        for (int nt = 0; nt < 8; nt++) {
            int row = row0 + wm*32 + mt*16 + (lane >> 2);
            int col = s0 + wn*64 + nt*8 + (lane & 3)*2;
            *(float2*)&g_s[(size_t)row*Tn + col]     = make_float2(c[mt][nt][0], c[mt][nt][1]);
            *(float2*)&g_s[(size_t)(row+8)*Tn + col] = make_float2(c[mt][nt][2], c[mt][nt][3]);
        }
    }
}

// ---------------------------------------------------------------------------
// Kernel B2: per-row stats: m8, 1/Z, 1/causal-den. One warp per row.
// ---------------------------------------------------------------------------
__global__ __launch_bounds__(256) void stats_kernel()
{
    const int row  = blockIdx.x * 8 + (threadIdx.x >> 5);
    const int lane = threadIdx.x & 31;
    const int t    = row & (Tn - 1);
    const float* zr = &g_s[(size_t)row * Tn];

    float4 v[16];
    #pragma unroll
    for (int w = 0; w < 16; w++)
        v[w] = *(const float4*)&zr[w*128 + lane*4];

    float m = -1e30f;
    #pragma unroll
    for (int w = 0; w < 16; w++)
        m = fmaxf(m, fmaxf(fmaxf(v[w].x, v[w].y), fmaxf(v[w].z, v[w].w)));
    #pragma unroll
    for (int off = 16; off > 0; off >>= 1)
        m = fmaxf(m, __shfl_xor_sync(0xffffffffu, m, off));
    const float m8 = 8.f * m;

    float Z = 0.f;
    #pragma unroll
    for (int w = 0; w < 16; w++) {
        v[w].x = __expf(fmaf(v[w].x, 8.f, -m8));
        v[w].y = __expf(fmaf(v[w].y, 8.f, -m8));
        v[w].z = __expf(fmaf(v[w].z, 8.f, -m8));
        v[w].w = __expf(fmaf(v[w].w, 8.f, -m8));
        Z += v[w].x + v[w].y + v[w].z + v[w].w;
    }
    #pragma unroll
    for (int off = 16; off > 0; off >>= 1)
        Z += __shfl_xor_sync(0xffffffffu, Z, off);
    const float iz = 1.f / Z;

    float den = 0.f;
    #pragma unroll
    for (int w = 0; w < 16; w++) {
        const int sbase = w*128 + lane*4;
        den += (sbase + 0 <= t) ? __expf(v[w].x * iz) : 0.f;
        den += (sbase + 1 <= t) ? __expf(v[w].y * iz) : 0.f;
        den += (sbase + 2 <= t) ? __expf(v[w].z * iz) : 0.f;
        den += (sbase + 3 <= t) ? __expf(v[w].w * iz) : 0.f;
    }
    #pragma unroll
    for (int off = 16; off > 0; off >>= 1)
        den += __shfl_xor_sync(0xffffffffu, den, off);

    if (lane == 0) {
        g_m8[row] = m8; g_iz[row] = iz; g_iden[row] = 1.f / den;
    }
}

// ---------------------------------------------------------------------------
// Kernel B3: split-s partial numerators, on-the-fly e. (f32x2 SIMT)
// ---------------------------------------------------------------------------
__global__ __launch_bounds__(128) void outp_kernel()
{
    const int chunk = blockIdx.x;
    const int row0  = blockIdx.y * 128;
    const int b     = row0 >> 11;
    const int t0    = row0 & (Tn - 1);
    const int sbeg  = chunk * CHUNK;
    if (sbeg > t0 + 127) return;
    const int send  = min(sbeg + CHUNK, t0 + 128);
    const int nk    = (send - sbeg) >> 5;

    __shared__ float eT[32][132];
    __shared__ float vs[32][68];

    const int tid = threadIdx.x;
    const int ty  = tid >> 3;
    const int tx  = tid & 7;
    const int lr  = tid;
    const int t_my = t0 + lr;

    const float m8 = g_m8[row0 + lr];
    const float iz = g_iz[row0 + lr];
    const float* zrow = &g_s[(size_t)(row0 + lr)*Tn];

    ull c2[4][8];
    #pragma unroll
    for (int i = 0; i < 4; i++)
        #pragma unroll
        for (int j = 0; j < 8; j++) c2[i][j] = 0ULL;

    for (int kt = 0; kt < nk; kt++) {
        const int s0 = sbeg + kt*32;
        __syncthreads();
        for (int i = tid; i < 512; i += 128) {
            int s = i >> 4, d4 = i & 15;
            *(float4*)&vs[s][d4*4] =
                *(const float4*)&g_v[(size_t)(b*Tn + s0 + s)*HDn + d4*4];
        }
        #pragma unroll
        for (int q = 0; q < 8; q++) {
            float4 z = *(const float4*)&zrow[s0 + q*4];
            float zz[4] = {z.x, z.y, z.z, z.w};
            #pragma unroll
            for (int c = 0; c < 4; c++) {
                int s = s0 + q*4 + c;
                float e = 0.f;
                if (s <= t_my)
                    e = __expf(__expf(fmaf(zz[c], 8.f, -m8)) * iz);
                eT[q*4 + c][lr] = e;
            }
        }
        __syncthreads();
        #pragma unroll 8
        for (int kk = 0; kk < 32; kk++) {
            ull a2[4];
            #pragma unroll
            for (int i = 0; i < 4; i++)
                a2[i] = *(const ull*)&eT[kk][ty*8 + 2*i];
            float4 bv0 = *(const float4*)&vs[kk][tx*4];
            float4 bv1 = *(const float4*)&vs[kk][32 + tx*4];
            ull b2[8] = { bcast2(bv0.x), bcast2(bv0.y), bcast2(bv0.z), bcast2(bv0.w),
                          bcast2(bv1.x), bcast2(bv1.y), bcast2(bv1.z), bcast2(bv1.w) };
            #pragma unroll
            for (int i = 0; i < 4; i++)
                #pragma unroll
                for (int j = 0; j < 8; j++)
                    fma2(c2[i][j], a2[i], b2[j]);
        }
    }

    float* dst = &g_part[((size_t)chunk*NROWS + row0)*HDn];
    #pragma unroll
    for (int i = 0; i < 4; i++) {
        float2 p[8];
        #pragma unroll
        for (int j = 0; j < 8; j++) p[j] = unpack2(c2[i][j]);
        #pragma unroll
        for (int h = 0; h < 2; h++) {
            int r = ty*8 + 2*i + h;
            float4 A, B;
            A.x = h ? p[0].y : p[0].x;  A.y = h ? p[1].y : p[1].x;
            A.z = h ? p[2].y : p[2].x;  A.w = h ? p[3].y : p[3].x;
            B.x = h ? p[4].y : p[4].x;  B.y = h ? p[5].y : p[5].x;
            B.z = h ? p[6].y : p[6].x;  B.w = h ? p[7].y : p[7].x;
            *(float4*)&dst[(size_t)r*HDn + tx*4]      = A;
            *(float4*)&dst[(size_t)r*HDn + 32 + tx*4] = B;
        }
    }
}

// ---------------------------------------------------------------------------
// Kernel B4: finalize.
// ---------------------------------------------------------------------------
__global__ __launch_bounds__(256) void fin_kernel(float* __restrict__ out)
{
    const int idx = blockIdx.x * 256 + threadIdx.x;
    const int row = idx >> 4;
    const int d4  = (idx & 15) * 4;
    const int nch = (((row & (Tn-1)) | 127) / CHUNK) + 1;

    float4 s = make_float4(0.f, 0.f, 0.f, 0.f);
    for (int c = 0; c < nch; c++) {
        float4 p = *(const float4*)&g_part[((size_t)c*NROWS + row)*HDn + d4];
        s.x += p.x; s.y += p.y; s.z += p.z; s.w += p.w;
    }
    const float inv = g_iden[row];
    s.x *= inv; s.y *= inv; s.z *= inv; s.w *= inv;
    *(float4*)&out[(size_t)row*HDn + d4] = s;
}

// ---------------------------------------------------------------------------
extern "C" void kernel_launch(void* const* d_in, const int* in_sizes, int n_in,
                              void* d_out, int out_size)
{
    const float* x  = (const float*)d_in[0];
    const float* Wq = (const float*)d_in[1];
    const float* Wk = (const float*)d_in[2];
    const float* Wv = (const float*)d_in[3];
    float* out = (float*)d_out;

    cudaFuncSetAttribute(scores_mma, cudaFuncAttributeMaxDynamicSharedMemorySize, SC_SMEM);

    qkv_kernel<<<dim3(2, NROWS/128), 128>>>(x, Wq, Wk, Wv);
    scores_mma<<<dim3(Tn/128, NROWS/128), 256, SC_SMEM>>>();
    stats_kernel<<<NROWS/8, 256>>>();
    outp_kernel<<<dim3(NCHUNK, NROWS/128), 128>>>();
    fin_kernel<<<(NROWS*HDn/4)/256, 256>>>(out);
}

// round 7
// speedup vs baseline: 1.7420x; 1.0962x over previous
#include <cuda_runtime.h>
#include <cuda_bf16.h>
#include <cstdint>

#define Bn 4
#define Tn 2048
#define Cn 1024
#define HDn 64
#define NROWS (Bn*Tn)       // 8192
#define CHUNK 256
#define NCHUNK (Tn/CHUNK)   // 8

typedef unsigned long long ull;
typedef unsigned short u16;

// Scratch (__device__ globals — allowed)
__device__ __nv_bfloat16 g_qhi[NROWS*HDn];
__device__ __nv_bfloat16 g_qlo[NROWS*HDn];
__device__ __nv_bfloat16 g_khi[NROWS*HDn];
__device__ __nv_bfloat16 g_klo[NROWS*HDn];
__device__ __nv_bfloat16 g_vhi[NROWS*HDn];
__device__ __nv_bfloat16 g_vlo[NROWS*HDn];
__device__ float g_s[NROWS*Tn];              // raw scores z (unscaled)
__device__ float g_m8[NROWS];                // 8 * rowmax(z)
__device__ float g_iz[NROWS];                // 1 / Z (first softmax)
__device__ float g_iden[NROWS];              // 1 / causal denominator
__device__ float g_part[NCHUNK*NROWS*HDn];   // split-s partial numerators

// ---- f32x2 helpers -------------------------------------------------------
__device__ __forceinline__ ull pack2(float x, float y) {
    ull r;
    asm("mov.b64 %0, {%1, %2};" : "=l"(r)
        : "r"(__float_as_uint(x)), "r"(__float_as_uint(y)));
    return r;
}
__device__ __forceinline__ ull bcast2(float x) { return pack2(x, x); }
__device__ __forceinline__ void fma2(ull& c, ull a, ull b) {
    asm("fma.rn.f32x2 %0, %1, %2, %0;" : "+l"(c) : "l"(a), "l"(b));
}
__device__ __forceinline__ float2 unpack2(ull v) {
    unsigned lo, hi;
    asm("mov.b64 {%0, %1}, %2;" : "=r"(lo), "=r"(hi) : "l"(v));
    return make_float2(__uint_as_float(lo), __uint_as_float(hi));
}

// ---- mma.sync helpers ----------------------------------------------------
__device__ __forceinline__ uint32_t smem_u32(const void* p) {
    uint32_t a;
    asm("{ .reg .u64 t; cvta.to.shared.u64 t, %1; cvt.u32.u64 %0, t; }"
        : "=r"(a) : "l"(p));
    return a;
}
#define SW128(o) ((o) ^ (((o) >> 3) & 0x70))

__device__ __forceinline__ void ldsm4(uint32_t* r, uint32_t addr) {
    asm volatile("ldmatrix.sync.aligned.m8n8.x4.shared.b16 {%0,%1,%2,%3}, [%4];"
                 : "=r"(r[0]), "=r"(r[1]), "=r"(r[2]), "=r"(r[3]) : "r"(addr));
}
__device__ __forceinline__ void mma16816(float* c, const uint32_t* a,
                                         uint32_t b0, uint32_t b1) {
    asm volatile("mma.sync.aligned.m16n8k16.row.col.f32.bf16.bf16.f32 "
                 "{%0,%1,%2,%3}, {%4,%5,%6,%7}, {%8,%9}, {%0,%1,%2,%3};"
                 : "+f"(c[0]), "+f"(c[1]), "+f"(c[2]), "+f"(c[3])
                 : "r"(a[0]), "r"(a[1]), "r"(a[2]), "r"(a[3]), "r"(b0), "r"(b1));
}

// ---------------------------------------------------------------------------
// Kernel A: QKV projection (f32x2 SIMT). Emits Q,K,V as bf16 hi/lo.
// ---------------------------------------------------------------------------
__global__ __launch_bounds__(128) void qkv_kernel(
    const float* __restrict__ x,
    const float* __restrict__ Wq,
    const float* __restrict__ Wk,
    const float* __restrict__ Wv)
{
    __shared__ float xs[32][132];
    __shared__ float ws[32][100];

    const int ch   = blockIdx.x;
    const int row0 = blockIdx.y * 128;
    const int tid  = threadIdx.x;
    const int ty   = tid >> 4;
    const int tx   = tid & 15;

    ull c2[8][6];
    #pragma unroll
    for (int i = 0; i < 8; i++)
        #pragma unroll
        for (int j = 0; j < 6; j++) c2[i][j] = 0ULL;

    for (int k0 = 0; k0 < Cn; k0 += 32) {
        __syncthreads();
        for (int i = tid; i < 128*8; i += 128) {
            int r = i >> 3, q = i & 7;
            float4 v = *(const float4*)&x[(size_t)(row0 + r)*Cn + k0 + q*4];
            xs[q*4+0][r] = v.x; xs[q*4+1][r] = v.y;
            xs[q*4+2][r] = v.z; xs[q*4+3][r] = v.w;
        }
        for (int i = tid; i < 32*24; i += 128) {
            int kk = i / 24, c4 = i - kk*24;
            int gc = ch*96 + c4*4;
            const float* W = (gc < 64) ? Wq : ((gc < 128) ? Wk : Wv);
            float4 v = *(const float4*)&W[(size_t)(k0+kk)*HDn + (gc & 63)];
            *(float4*)&ws[kk][c4*4] = v;
        }
        __syncthreads();
        #pragma unroll 8
        for (int kk = 0; kk < 32; kk++) {
            ull a2[8];
            #pragma unroll
            for (int q = 0; q < 8; q++)
                a2[q] = *(const ull*)&xs[kk][ty*16 + 2*q];
            ull b2[6];
            #pragma unroll
            for (int j = 0; j < 6; j++)
                b2[j] = bcast2(ws[kk][tx*6 + j]);
            #pragma unroll
            for (int q = 0; q < 8; q++)
                #pragma unroll
                for (int j = 0; j < 6; j++)
                    fma2(c2[q][j], a2[q], b2[j]);
        }
    }
    #pragma unroll
    for (int q = 0; q < 8; q++) {
        #pragma unroll
        for (int j = 0; j < 6; j++) {
            float2 v = unpack2(c2[q][j]);
            int gc = ch*96 + tx*6 + j;
            int dcol = gc & 63;
            size_t r = (size_t)(row0 + ty*16 + 2*q);
            float vv[2] = {v.x, v.y};
            #pragma unroll
            for (int h = 0; h < 2; h++) {
                size_t o = (r + h)*HDn + dcol;
                __nv_bfloat16 hi = __float2bfloat16(vv[h]);
                __nv_bfloat16 lo = __float2bfloat16(vv[h] - __bfloat162float(hi));
                if      (gc < 64)  { g_qhi[o] = hi; g_qlo[o] = lo; }
                else if (gc < 128) { g_khi[o] = hi; g_klo[o] = lo; }
                else               { g_vhi[o] = hi; g_vlo[o] = lo; }
            }
        }
    }
}

// ---------------------------------------------------------------------------
// Kernel B1: scores via warp-level mma.sync (bf16 split, fp32 accum).
// ---------------------------------------------------------------------------
#define SC_QHI     0
#define SC_QLO     (SC_QHI + 16384)
#define SC_KHI     (SC_QLO + 16384)
#define SC_KLO     (SC_KHI + 16384)
#define SC_SMEM    (SC_KLO + 16384)

__device__ __forceinline__ void sc_load_tile(char* smem, int dstoff,
    const __nv_bfloat16* __restrict__ src, int row0, int tid)
{
    #pragma unroll
    for (int c = tid; c < 1024; c += 256) {
        int r = c >> 3, o = (c & 7) * 16;
        uint4 v = *(const uint4*)((const char*)(src + (size_t)(row0 + r)*HDn) + o);
        *(uint4*)(smem + dstoff + SW128(r*128 + o)) = v;
    }
}

__global__ __launch_bounds__(256) void scores_mma()
{
    extern __shared__ char smem[];
    const uint32_t sb = smem_u32(smem);
    const int tid  = threadIdx.x;
    const int wid  = tid >> 5;
    const int lane = tid & 31;

    const int s0    = blockIdx.x * 128;
    const int row0  = blockIdx.y * 128;
    const int b     = row0 >> 11;
    const int krow0 = b * Tn + s0;

    sc_load_tile(smem, SC_QHI, g_qhi, row0, tid);
    sc_load_tile(smem, SC_QLO, g_qlo, row0, tid);
    sc_load_tile(smem, SC_KHI, g_khi, krow0, tid);
    sc_load_tile(smem, SC_KLO, g_klo, krow0, tid);
    __syncthreads();

    const int wm = wid & 3;
    const int wn = wid >> 2;

    float c[2][8][4];
    #pragma unroll
    for (int mt = 0; mt < 2; mt++)
        #pragma unroll
        for (int nt = 0; nt < 8; nt++)
            #pragma unroll
            for (int q = 0; q < 4; q++) c[mt][nt][q] = 0.f;

    const int lrow = lane & 15;
    const int lcol = (lane >> 4) * 16;

    #pragma unroll
    for (int k = 0; k < 4; k++) {
        const int kb = k * 32;
        uint32_t ahi[2][4], alo[2][4];
        #pragma unroll
        for (int mt = 0; mt < 2; mt++) {
            int r = wm*32 + mt*16 + lrow;
            ldsm4(ahi[mt], sb + SC_QHI + SW128(r*128 + kb + lcol));
            ldsm4(alo[mt], sb + SC_QLO + SW128(r*128 + kb + lcol));
        }
        #pragma unroll
        for (int nt2 = 0; nt2 < 4; nt2++) {
            int r = wn*64 + nt2*16 + lrow;
            uint32_t bh[4], bl[4];
            ldsm4(bh, sb + SC_KHI + SW128(r*128 + kb + lcol));
            ldsm4(bl, sb + SC_KLO + SW128(r*128 + kb + lcol));
            #pragma unroll
            for (int mt = 0; mt < 2; mt++) {
                float* c0 = c[mt][nt2*2+0];
                float* c1 = c[mt][nt2*2+1];
                mma16816(c0, ahi[mt], bh[0], bh[2]);
                mma16816(c1, ahi[mt], bh[1], bh[3]);
                mma16816(c0, ahi[mt], bl[0], bl[2]);
                mma16816(c1, ahi[mt], bl[1], bl[3]);
                mma16816(c0, alo[mt], bh[0], bh[2]);
                mma16816(c1, alo[mt], bh[1], bh[3]);
            }
        }
    }

    #pragma unroll
    for (int mt = 0; mt < 2; mt++) {
        #pragma unroll
        for (int nt = 0; nt < 8; nt++) {
            int row = row0 + wm*32 + mt*16 + (lane >> 2);
            int col = s0 + wn*64 + nt*8 + (lane & 3)*2;
            *(float2*)&g_s[(size_t)row*Tn + col]     = make_float2(c[mt][nt][0], c[mt][nt][1]);
            *(float2*)&g_s[(size_t)(row+8)*Tn + col] = make_float2(c[mt][nt][2], c[mt][nt][3]);
        }
    }
}

// ---------------------------------------------------------------------------
// Kernel B2: per-row stats: m8, 1/Z, 1/causal-den. One warp per row.
// ---------------------------------------------------------------------------
__global__ __launch_bounds__(256) void stats_kernel()
{
    const int row  = blockIdx.x * 8 + (threadIdx.x >> 5);
    const int lane = threadIdx.x & 31;
    const int t    = row & (Tn - 1);
    const float* zr = &g_s[(size_t)row * Tn];

    float4 v[16];
    #pragma unroll
    for (int w = 0; w < 16; w++)
        v[w] = *(const float4*)&zr[w*128 + lane*4];

    float m = -1e30f;
    #pragma unroll
    for (int w = 0; w < 16; w++)
        m = fmaxf(m, fmaxf(fmaxf(v[w].x, v[w].y), fmaxf(v[w].z, v[w].w)));
    #pragma unroll
    for (int off = 16; off > 0; off >>= 1)
        m = fmaxf(m, __shfl_xor_sync(0xffffffffu, m, off));
    const float m8 = 8.f * m;

    float Z = 0.f;
    #pragma unroll
    for (int w = 0; w < 16; w++) {
        v[w].x = __expf(fmaf(v[w].x, 8.f, -m8));
        v[w].y = __expf(fmaf(v[w].y, 8.f, -m8));
        v[w].z = __expf(fmaf(v[w].z, 8.f, -m8));
        v[w].w = __expf(fmaf(v[w].w, 8.f, -m8));
        Z += v[w].x + v[w].y + v[w].z + v[w].w;
    }
    #pragma unroll
    for (int off = 16; off > 0; off >>= 1)
        Z += __shfl_xor_sync(0xffffffffu, Z, off);
    const float iz = 1.f / Z;

    float den = 0.f;
    #pragma unroll
    for (int w = 0; w < 16; w++) {
        const int sbase = w*128 + lane*4;
        den += (sbase + 0 <= t) ? __expf(v[w].x * iz) : 0.f;
        den += (sbase + 1 <= t) ? __expf(v[w].y * iz) : 0.f;
        den += (sbase + 2 <= t) ? __expf(v[w].z * iz) : 0.f;
        den += (sbase + 3 <= t) ? __expf(v[w].w * iz) : 0.f;
    }
    #pragma unroll
    for (int off = 16; off > 0; off >>= 1)
        den += __shfl_xor_sync(0xffffffffu, den, off);

    if (lane == 0) {
        g_m8[row] = m8; g_iz[row] = iz; g_iden[row] = 1.f / den;
    }
}

// ---------------------------------------------------------------------------
// Kernel B3: split-s partial numerators via HMMA (split-bf16 e and V).
// CTA: 128 rows x 64 d; 8 warps (4m x 2n), warp tile 32 rows x 32 d.
// Per 32-s tile: regenerate e -> bf16 hi/lo smem; V^T tiles hi/lo smem.
// num += ehi vhi + ehi vlo + elo vhi   (fp32 accum).
// ---------------------------------------------------------------------------
#define ESTR 40   // halves per e row (pad 32 -> 40)
#define VSTR 40   // halves per vT row

__global__ __launch_bounds__(256) void outp_mma()
{
    __shared__ u16 ehi[128*ESTR];
    __shared__ u16 elo[128*ESTR];
    __shared__ u16 vThi[64*VSTR];
    __shared__ u16 vTlo[64*VSTR];

    const int chunk = blockIdx.x;
    const int row0  = blockIdx.y * 128;
    const int b     = row0 >> 11;
    const int t0    = row0 & (Tn - 1);
    const int sbeg  = chunk * CHUNK;
    if (sbeg > t0 + 127) return;
    const int send  = min(sbeg + CHUNK, t0 + 128);
    const int nk    = (send - sbeg) >> 5;

    const int tid  = threadIdx.x;
    const int wid  = tid >> 5;
    const int lane = tid & 31;
    const int wm   = wid & 3;          // rows wm*32..+31
    const int wn   = wid >> 2;         // d cols wn*32..+31

    // e-gen assignment: thread -> (row, 16-s half)
    const int myrow = tid >> 1;
    const int shalf = (tid & 1) * 16;
    const int t_my  = t0 + myrow;
    const float m8  = g_m8[row0 + myrow];
    const float iz  = g_iz[row0 + myrow];
    const float* zrow = &g_s[(size_t)(row0 + myrow)*Tn];

    const uint32_t sb_ehi = smem_u32(ehi);
    const uint32_t sb_elo = smem_u32(elo);
    const uint32_t sb_vhi = smem_u32(vThi);
    const uint32_t sb_vlo = smem_u32(vTlo);

    float c[2][4][4];
    #pragma unroll
    for (int mt = 0; mt < 2; mt++)
        #pragma unroll
        for (int nt = 0; nt < 4; nt++)
            #pragma unroll
            for (int q = 0; q < 4; q++) c[mt][nt][q] = 0.f;

    const int lrow  = lane & 15;
    const int lcolb = (lane >> 4) * 16;   // byte offset within 16x16 tile row

    for (int kt = 0; kt < nk; kt++) {
        const int s0 = sbeg + kt*32;
        __syncthreads();
        // ---- V^T tiles: read [s][d] hi/lo, scatter transposed to [d][s]
        for (int i = tid; i < 256; i += 256) {
            int s  = i >> 3;
            int d0 = (i & 7) * 8;
            const size_t go = (size_t)(b*Tn + s0 + s)*HDn + d0;
            uint4 hv = *(const uint4*)&g_vhi[go];
            uint4 lv = *(const uint4*)&g_vlo[go];
            const u16* hp = (const u16*)&hv;
            const u16* lp = (const u16*)&lv;
            #pragma unroll
            for (int j = 0; j < 8; j++) {
                vThi[(d0 + j)*VSTR + s] = hp[j];
                vTlo[(d0 + j)*VSTR + s] = lp[j];
            }
        }
        // ---- e tile: 16 entries per thread, split to bf16 hi/lo
        {
            const float* zp = &zrow[s0 + shalf];
            #pragma unroll
            for (int q = 0; q < 4; q++) {
                float4 z = *(const float4*)&zp[q*4];
                float zz[4] = {z.x, z.y, z.z, z.w};
                #pragma unroll
                for (int c4 = 0; c4 < 4; c4++) {
                    int s = s0 + shalf + q*4 + c4;
                    float e = 0.f;
                    if (s <= t_my)
                        e = __expf(__expf(fmaf(zz[c4], 8.f, -m8)) * iz);
                    __nv_bfloat16 hi = __float2bfloat16(e);
                    __nv_bfloat16 lo = __float2bfloat16(e - __bfloat162float(hi));
                    int so = myrow*ESTR + shalf + q*4 + c4;
                    ehi[so] = *(const u16*)&hi;
                    elo[so] = *(const u16*)&lo;
                }
            }
        }
        __syncthreads();
        // ---- HMMA: two k16 sub-steps
        #pragma unroll
        for (int ks = 0; ks < 2; ks++) {
            const int kb = ks * 32;   // byte offset of k-sub within 32-s tile
            uint32_t ah[2][4], al[2][4];
            #pragma unroll
            for (int mt = 0; mt < 2; mt++) {
                int r = wm*32 + mt*16 + lrow;
                uint32_t base = r*(ESTR*2) + kb + lcolb;
                ldsm4(ah[mt], sb_ehi + base);
                ldsm4(al[mt], sb_elo + base);
            }
            uint32_t bh[2][4], bl[2][4];
            #pragma unroll
            for (int ng = 0; ng < 2; ng++) {
                int d = wn*32 + ng*16 + lrow;
                uint32_t base = d*(VSTR*2) + kb + lcolb;
                ldsm4(bh[ng], sb_vhi + base);
                ldsm4(bl[ng], sb_vlo + base);
            }
            #pragma unroll
            for (int mt = 0; mt < 2; mt++) {
                #pragma unroll
                for (int ng = 0; ng < 2; ng++) {
                    float* c0 = c[mt][ng*2+0];
                    float* c1 = c[mt][ng*2+1];
                    mma16816(c0, ah[mt], bh[ng][0], bh[ng][2]);
                    mma16816(c1, ah[mt], bh[ng][1], bh[ng][3]);
                    mma16816(c0, ah[mt], bl[ng][0], bl[ng][2]);
                    mma16816(c1, ah[mt], bl[ng][1], bl[ng][3]);
                    mma16816(c0, al[mt], bh[ng][0], bh[ng][2]);
                    mma16816(c1, al[mt], bh[ng][1], bh[ng][3]);
                }
            }
        }
    }

    // epilogue -> g_part[chunk]
    float* dst = &g_part[((size_t)chunk*NROWS + row0)*HDn];
    #pragma unroll
    for (int mt = 0; mt < 2; mt++) {
        #pragma unroll
        for (int nt = 0; nt < 4; nt++) {
            int r   = wm*32 + mt*16 + (lane >> 2);
            int col = wn*32 + nt*8 + (lane & 3)*2;
            *(float2*)&dst[(size_t)r*HDn + col]     = make_float2(c[mt][nt][0], c[mt][nt][1]);
            *(float2*)&dst[(size_t)(r+8)*HDn + col] = make_float2(c[mt][nt][2], c[mt][nt][3]);
        }
    }
}

// ---------------------------------------------------------------------------
// Kernel B4: finalize.
// ---------------------------------------------------------------------------
__global__ __launch_bounds__(256) void fin_kernel(float* __restrict__ out)
{
    const int idx = blockIdx.x * 256 + threadIdx.x;
    const int row = idx >> 4;
    const int d4  = (idx & 15) * 4;
    const int nch = (((row & (Tn-1)) | 127) / CHUNK) + 1;

    float4 s = make_float4(0.f, 0.f, 0.f, 0.f);
    for (int c = 0; c < nch; c++) {
        float4 p = *(const float4*)&g_part[((size_t)c*NROWS + row)*HDn + d4];
        s.x += p.x; s.y += p.y; s.z += p.z; s.w += p.w;
    }
    const float inv = g_iden[row];
    s.x *= inv; s.y *= inv; s.z *= inv; s.w *= inv;
    *(float4*)&out[(size_t)row*HDn + d4] = s;
}

// ---------------------------------------------------------------------------
extern "C" void kernel_launch(void* const* d_in, const int* in_sizes, int n_in,
                              void* d_out, int out_size)
{
    const float* x  = (const float*)d_in[0];
    const float* Wq = (const float*)d_in[1];
    const float* Wk = (const float*)d_in[2];
    const float* Wv = (const float*)d_in[3];
    float* out = (float*)d_out;

    cudaFuncSetAttribute(scores_mma, cudaFuncAttributeMaxDynamicSharedMemorySize, SC_SMEM);

    qkv_kernel<<<dim3(2, NROWS/128), 128>>>(x, Wq, Wk, Wv);
    scores_mma<<<dim3(Tn/128, NROWS/128), 256, SC_SMEM>>>();
    stats_kernel<<<NROWS/8, 256>>>();
    outp_mma<<<dim3(NCHUNK, NROWS/128), 256>>>();
    fin_kernel<<<(NROWS*HDn/4)/256, 256>>>(out);
}

// round 10
// speedup vs baseline: 3.5861x; 2.0586x over previous
#include <cuda_runtime.h>
#include <cuda_bf16.h>
#include <cstdint>

#define Bn 4
#define Tn 2048
#define Cn 1024
#define HDn 64
#define NROWS (Bn*Tn)       // 8192
#define CHUNK 256
#define NCHUNK (Tn/CHUNK)   // 8

typedef unsigned short u16;

// Scratch (__device__ globals — allowed)
__device__ __nv_bfloat16 g_xhi[NROWS*Cn];
__device__ __nv_bfloat16 g_xlo[NROWS*Cn];
__device__ __nv_bfloat16 g_whi[Cn*192];      // [k][Q|K|V cols]
__device__ __nv_bfloat16 g_wlo[Cn*192];
__device__ __nv_bfloat16 g_qhi[NROWS*HDn];
__device__ __nv_bfloat16 g_qlo[NROWS*HDn];
__device__ __nv_bfloat16 g_khi[NROWS*HDn];
__device__ __nv_bfloat16 g_klo[NROWS*HDn];
__device__ __nv_bfloat16 g_vhi[NROWS*HDn];
__device__ __nv_bfloat16 g_vlo[NROWS*HDn];
__device__ float g_s[NROWS*Tn];              // raw scores z (unscaled)
__device__ __nv_bfloat16 g_ehi[NROWS*Tn];    // e = exp(w1), causal, bf16 hi
__device__ __nv_bfloat16 g_elo[NROWS*Tn];    // bf16 lo
__device__ float g_iden[NROWS];              // 1 / causal denominator
__device__ float g_part[NCHUNK*NROWS*HDn];   // split-s partial numerators

// ---- mma.sync helpers ----------------------------------------------------
__device__ __forceinline__ uint32_t smem_u32(const void* p) {
    uint32_t a;
    asm("{ .reg .u64 t; cvta.to.shared.u64 t, %1; cvt.u32.u64 %0, t; }"
        : "=r"(a) : "l"(p));
    return a;
}
#define SW128(o) ((o) ^ (((o) >> 3) & 0x70))

__device__ __forceinline__ void ldsm4(uint32_t* r, uint32_t addr) {
    asm volatile("ldmatrix.sync.aligned.m8n8.x4.shared.b16 {%0,%1,%2,%3}, [%4];"
                 : "=r"(r[0]), "=r"(r[1]), "=r"(r[2]), "=r"(r[3]) : "r"(addr));
}
__device__ __forceinline__ void ldsm4t(uint32_t* r, uint32_t addr) {
    asm volatile("ldmatrix.sync.aligned.m8n8.x4.trans.shared.b16 {%0,%1,%2,%3}, [%4];"
                 : "=r"(r[0]), "=r"(r[1]), "=r"(r[2]), "=r"(r[3]) : "r"(addr));
}
__device__ __forceinline__ void mma16816(float* c, const uint32_t* a,
                                         uint32_t b0, uint32_t b1) {
    asm volatile("mma.sync.aligned.m16n8k16.row.col.f32.bf16.bf16.f32 "
                 "{%0,%1,%2,%3}, {%4,%5,%6,%7}, {%8,%9}, {%0,%1,%2,%3};"
                 : "+f"(c[0]), "+f"(c[1]), "+f"(c[2]), "+f"(c[3])
                 : "r"(a[0]), "r"(a[1]), "r"(a[2]), "r"(a[3]), "r"(b0), "r"(b1));
}
__device__ __forceinline__ uint32_t bfsplit(float v, u16& lo16) {
    __nv_bfloat16 hi = __float2bfloat16(v);
    __nv_bfloat16 lo = __float2bfloat16(v - __bfloat162float(hi));
    lo16 = *(const u16*)&lo;
    return *(const u16*)&hi;
}

// ---------------------------------------------------------------------------
// prep_x: split x (fp32) -> bf16 hi/lo.  8 elems per thread.
// ---------------------------------------------------------------------------
__global__ __launch_bounds__(256) void prep_x(const float* __restrict__ x)
{
    const size_t i8 = ((size_t)blockIdx.x * 256 + threadIdx.x) * 8;
    float4 a = *(const float4*)&x[i8];
    float4 b = *(const float4*)&x[i8 + 4];
    float v[8] = {a.x,a.y,a.z,a.w,b.x,b.y,b.z,b.w};
    u16 hi[8], lo[8];
    #pragma unroll
    for (int j = 0; j < 8; j++) { hi[j] = (u16)bfsplit(v[j], lo[j]); }
    *(uint4*)&g_xhi[i8] = *(const uint4*)hi;
    *(uint4*)&g_xlo[i8] = *(const uint4*)lo;
}

// ---------------------------------------------------------------------------
// prep_w: split Wq|Wk|Wv into combined [k][192] bf16 hi/lo.
// ---------------------------------------------------------------------------
__global__ __launch_bounds__(256) void prep_w(
    const float* __restrict__ Wq, const float* __restrict__ Wk,
    const float* __restrict__ Wv)
{
    const int i8 = (blockIdx.x * 256 + threadIdx.x) * 8;   // over 1024*192
    if (i8 >= Cn*192) return;
    const int k    = i8 / 192;
    const int col8 = i8 - k*192;
    const float* W = (col8 < 64) ? Wq : ((col8 < 128) ? Wk : Wv);
    const float* src = &W[(size_t)k*HDn + (col8 & 63)];
    float4 a = *(const float4*)&src[0];
    float4 b = *(const float4*)&src[4];
    float v[8] = {a.x,a.y,a.z,a.w,b.x,b.y,b.z,b.w};
    u16 hi[8], lo[8];
    #pragma unroll
    for (int j = 0; j < 8; j++) { hi[j] = (u16)bfsplit(v[j], lo[j]); }
    *(uint4*)&g_whi[i8] = *(const uint4*)hi;
    *(uint4*)&g_wlo[i8] = *(const uint4*)lo;
}

// ---------------------------------------------------------------------------
// qkv_mma: [8192,1024] @ [1024,192] via HMMA, 3-term bf16 split.
// grid (2 col-halves of 96, 128 row-blocks of 64); 256 thr; 8 warps 4m x 2n;
// warp tile 16 rows x 48 cols.  K staged 32 at a time.
// ---------------------------------------------------------------------------
#define XSTR 40    // halves per x row (32 -> 40)
#define WSTR 104   // halves per w row (96 -> 104)

__global__ __launch_bounds__(256) void qkv_mma()
{
    __shared__ u16 sxh[64*XSTR], sxl[64*XSTR];
    __shared__ u16 swh[32*WSTR], swl[32*WSTR];

    const int ch   = blockIdx.x;
    const int row0 = blockIdx.y * 64;
    const int col0 = ch * 96;
    const int tid  = threadIdx.x;
    const int wid  = tid >> 5;
    const int lane = tid & 31;
    const int wm   = wid & 3;        // rows wm*16..+15
    const int wn   = wid >> 2;       // cols wn*48..+47

    const uint32_t sb_xh = smem_u32(sxh), sb_xl = smem_u32(sxl);
    const uint32_t sb_wh = smem_u32(swh), sb_wl = smem_u32(swl);

    float c[6][4];
    #pragma unroll
    for (int nt = 0; nt < 6; nt++)
        #pragma unroll
        for (int q = 0; q < 4; q++) c[nt][q] = 0.f;

    const int lrow  = lane & 15;
    const int lcolb = (lane >> 4) * 16;

    for (int k0 = 0; k0 < Cn; k0 += 32) {
        __syncthreads();
        // x tile: 64 rows x 32 k halves
        {
            int r = tid >> 2, c8 = (tid & 3) * 8;
            size_t go = (size_t)(row0 + r)*Cn + k0 + c8;
            *(uint4*)&sxh[r*XSTR + c8] = *(const uint4*)&g_xhi[go];
            *(uint4*)&sxl[r*XSTR + c8] = *(const uint4*)&g_xlo[go];
        }
        // W tile: 32 k x 96 cols
        for (int i = tid; i < 384; i += 256) {
            int r = i / 12, c8 = (i % 12) * 8;
            size_t go = (size_t)(k0 + r)*192 + col0 + c8;
            *(uint4*)&swh[r*WSTR + c8] = *(const uint4*)&g_whi[go];
            *(uint4*)&swl[r*WSTR + c8] = *(const uint4*)&g_wlo[go];
        }
        __syncthreads();
        #pragma unroll
        for (int ks = 0; ks < 2; ks++) {
            uint32_t ah[4], al[4];
            {
                uint32_t base = (wm*16 + lrow)*(XSTR*2) + ks*32 + lcolb;
                ldsm4(ah, sb_xh + base);
                ldsm4(al, sb_xl + base);
            }
            uint32_t bh[3][4], bl[3][4];
            #pragma unroll
            for (int ng = 0; ng < 3; ng++) {
                uint32_t base = (ks*16 + lrow)*(WSTR*2) + (wn*48 + ng*16)*2 + lcolb;
                ldsm4t(bh[ng], sb_wh + base);
                ldsm4t(bl[ng], sb_wl + base);
            }
            #pragma unroll
            for (int ng = 0; ng < 3; ng++) {
                float* c0 = c[ng*2+0];
                float* c1 = c[ng*2+1];
                mma16816(c0, ah, bh[ng][0], bh[ng][1]);
                mma16816(c1, ah, bh[ng][2], bh[ng][3]);
                mma16816(c0, ah, bl[ng][0], bl[ng][1]);
                mma16816(c1, ah, bl[ng][2], bl[ng][3]);
                mma16816(c0, al, bh[ng][0], bh[ng][1]);
                mma16816(c1, al, bh[ng][2], bh[ng][3]);
            }
        }
    }

    // epilogue: split to bf16 hi/lo, scatter to q/k/v
    #pragma unroll
    for (int nt = 0; nt < 6; nt++) {
        #pragma unroll
        for (int h = 0; h < 2; h++) {
            int r   = row0 + wm*16 + (lane >> 2) + h*8;
            int gc  = col0 + wn*48 + nt*8 + (lane & 3)*2;
            float v0 = c[nt][h*2+0], v1 = c[nt][h*2+1];
            u16 lo0, lo1;
            u16 hi0 = (u16)bfsplit(v0, lo0);
            u16 hi1 = (u16)bfsplit(v1, lo1);
            uint32_t hip = (uint32_t)hi0 | ((uint32_t)hi1 << 16);
            uint32_t lop = (uint32_t)lo0 | ((uint32_t)lo1 << 16);
            int dcol = gc & 63;
            size_t o = (size_t)r*HDn + dcol;
            if      (gc < 64)  { *(uint32_t*)&g_qhi[o] = hip; *(uint32_t*)&g_qlo[o] = lop; }
            else if (gc < 128) { *(uint32_t*)&g_khi[o] = hip; *(uint32_t*)&g_klo[o] = lop; }
            else               { *(uint32_t*)&g_vhi[o] = hip; *(uint32_t*)&g_vlo[o] = lop; }
        }
    }
}

// ---------------------------------------------------------------------------
// Kernel B1: scores via warp-level mma.sync (bf16 split, fp32 accum).
// ---------------------------------------------------------------------------
#define SC_QHI     0
#define SC_QLO     (SC_QHI + 16384)
#define SC_KHI     (SC_QLO + 16384)
#define SC_KLO     (SC_KHI + 16384)
#define SC_SMEM    (SC_KLO + 16384)

__device__ __forceinline__ void sc_load_tile(char* smem, int dstoff,
    const __nv_bfloat16* __restrict__ src, int row0, int tid)
{
    #pragma unroll
    for (int c = tid; c < 1024; c += 256) {
        int r = c >> 3, o = (c & 7) * 16;
        uint4 v = *(const uint4*)((const char*)(src + (size_t)(row0 + r)*HDn) + o);
        *(uint4*)(smem + dstoff + SW128(r*128 + o)) = v;
    }
}

__global__ __launch_bounds__(256) void scores_mma()
{
    extern __shared__ char smem[];
    const uint32_t sb = smem_u32(smem);
    const int tid  = threadIdx.x;
    const int wid  = tid >> 5;
    const int lane = tid & 31;

    const int s0    = blockIdx.x * 128;
    const int row0  = blockIdx.y * 128;
    const int b     = row0 >> 11;
    const int krow0 = b * Tn + s0;

    sc_load_tile(smem, SC_QHI, g_qhi, row0, tid);
    sc_load_tile(smem, SC_QLO, g_qlo, row0, tid);
    sc_load_tile(smem, SC_KHI, g_khi, krow0, tid);
    sc_load_tile(smem, SC_KLO, g_klo, krow0, tid);
    __syncthreads();

    const int wm = wid & 3;
    const int wn = wid >> 2;

    float c[2][8][4];
    #pragma unroll
    for (int mt = 0; mt < 2; mt++)
        #pragma unroll
        for (int nt = 0; nt < 8; nt++)
            #pragma unroll
            for (int q = 0; q < 4; q++) c[mt][nt][q] = 0.f;

    const int lrow = lane & 15;
    const int lcol = (lane >> 4) * 16;

    #pragma unroll
    for (int k = 0; k < 4; k++) {
        const int kb = k * 32;
        uint32_t ahi[2][4], alo[2][4];
        #pragma unroll
        for (int mt = 0; mt < 2; mt++) {
            int r = wm*32 + mt*16 + lrow;
            ldsm4(ahi[mt], sb + SC_QHI + SW128(r*128 + kb + lcol));
            ldsm4(alo[mt], sb + SC_QLO + SW128(r*128 + kb + lcol));
        }
        #pragma unroll
        for (int nt2 = 0; nt2 < 4; nt2++) {
            int r = wn*64 + nt2*16 + lrow;
            uint32_t bh[4], bl[4];
            ldsm4(bh, sb + SC_KHI + SW128(r*128 + kb + lcol));
            ldsm4(bl, sb + SC_KLO + SW128(r*128 + kb + lcol));
            #pragma unroll
            for (int mt = 0; mt < 2; mt++) {
                float* c0 = c[mt][nt2*2+0];
                float* c1 = c[mt][nt2*2+1];
                mma16816(c0, ahi[mt], bh[0], bh[2]);
                mma16816(c1, ahi[mt], bh[1], bh[3]);
                mma16816(c0, ahi[mt], bl[0], bl[2]);
                mma16816(c1, ahi[mt], bl[1], bl[3]);
                mma16816(c0, alo[mt], bh[0], bh[2]);
                mma16816(c1, alo[mt], bh[1], bh[3]);
            }
        }
    }

    #pragma unroll
    for (int mt = 0; mt < 2; mt++) {
        #pragma unroll
        for (int nt = 0; nt < 8; nt++) {
            int row = row0 + wm*32 + mt*16 + (lane >> 2);
            int col = s0 + wn*64 + nt*8 + (lane & 3)*2;
            *(float2*)&g_s[(size_t)row*Tn + col]     = make_float2(c[mt][nt][0], c[mt][nt][1]);
            *(float2*)&g_s[(size_t)(row+8)*Tn + col] = make_float2(c[mt][nt][2], c[mt][nt][3]);
        }
    }
}

// ---------------------------------------------------------------------------
// Kernel B2: per-row stats + e materialization.
// m8 = 8*max, iz = 1/Z, den = causal sum of e; writes e (bf16 hi/lo, 0 above
// diagonal) and 1/den.  One warp per row.
// ---------------------------------------------------------------------------
__global__ __launch_bounds__(256) void stats_kernel()
{
    const int row  = blockIdx.x * 8 + (threadIdx.x >> 5);
    const int lane = threadIdx.x & 31;
    const int t    = row & (Tn - 1);
    const float* zr = &g_s[(size_t)row * Tn];

    float4 v[16];
    #pragma unroll
    for (int w = 0; w < 16; w++)
        v[w] = *(const float4*)&zr[w*128 + lane*4];

    float m = -1e30f;
    #pragma unroll
    for (int w = 0; w < 16; w++)
        m = fmaxf(m, fmaxf(fmaxf(v[w].x, v[w].y), fmaxf(v[w].z, v[w].w)));
    #pragma unroll
    for (int off = 16; off > 0; off >>= 1)
        m = fmaxf(m, __shfl_xor_sync(0xffffffffu, m, off));
    const float m8 = 8.f * m;

    float Z = 0.f;
    #pragma unroll
    for (int w = 0; w < 16; w++) {
        v[w].x = __expf(fmaf(v[w].x, 8.f, -m8));
        v[w].y = __expf(fmaf(v[w].y, 8.f, -m8));
        v[w].z = __expf(fmaf(v[w].z, 8.f, -m8));
        v[w].w = __expf(fmaf(v[w].w, 8.f, -m8));
        Z += v[w].x + v[w].y + v[w].z + v[w].w;
    }
    #pragma unroll
    for (int off = 16; off > 0; off >>= 1)
        Z += __shfl_xor_sync(0xffffffffu, Z, off);
    const float iz = 1.f / Z;

    float den = 0.f;
    #pragma unroll
    for (int w = 0; w < 16; w++) {
        const int sbase = w*128 + lane*4;
        float e0 = (sbase + 0 <= t) ? __expf(v[w].x * iz) : 0.f;
        float e1 = (sbase + 1 <= t) ? __expf(v[w].y * iz) : 0.f;
        float e2 = (sbase + 2 <= t) ? __expf(v[w].z * iz) : 0.f;
        float e3 = (sbase + 3 <= t) ? __expf(v[w].w * iz) : 0.f;
        den += e0 + e1 + e2 + e3;
        u16 hi[4], lo[4];
        hi[0] = (u16)bfsplit(e0, lo[0]);
        hi[1] = (u16)bfsplit(e1, lo[1]);
        hi[2] = (u16)bfsplit(e2, lo[2]);
        hi[3] = (u16)bfsplit(e3, lo[3]);
        *(uint2*)&g_ehi[(size_t)row*Tn + sbase] = *(const uint2*)hi;
        *(uint2*)&g_elo[(size_t)row*Tn + sbase] = *(const uint2*)lo;
    }
    #pragma unroll
    for (int off = 16; off > 0; off >>= 1)
        den += __shfl_xor_sync(0xffffffffu, den, off);

    if (lane == 0) g_iden[row] = 1.f / den;
}

// ---------------------------------------------------------------------------
// Kernel B3: split-s partial numerators — pure staged HMMA GEMM.
// CTA: 128 rows x 64 d; 8 warps (4m x 2n); e from g_ehi/g_elo (A, non-trans),
// V from g_vhi/g_vlo (B, trans ldmatrix from [s][d]).
// ---------------------------------------------------------------------------
#define ESTR 40   // halves per e row (32 -> 40)
#define VSTR 72   // halves per v row (64 -> 72)

__global__ __launch_bounds__(256) void outp_mma()
{
    __shared__ u16 seh[128*ESTR], sel[128*ESTR];
    __shared__ u16 svh[32*VSTR],  svl[32*VSTR];

    const int chunk = blockIdx.x;
    const int row0  = blockIdx.y * 128;
    const int b     = row0 >> 11;
    const int t0    = row0 & (Tn - 1);
    const int sbeg  = chunk * CHUNK;
    if (sbeg > t0 + 127) return;
    const int send  = min(sbeg + CHUNK, t0 + 128);
    const int nk    = (send - sbeg) >> 5;

    const int tid  = threadIdx.x;
    const int wid  = tid >> 5;
    const int lane = tid & 31;
    const int wm   = wid & 3;
    const int wn   = wid >> 2;

    const uint32_t sb_eh = smem_u32(seh), sb_el = smem_u32(sel);
    const uint32_t sb_vh = smem_u32(svh), sb_vl = smem_u32(svl);

    float c[2][4][4];
    #pragma unroll
    for (int mt = 0; mt < 2; mt++)
        #pragma unroll
        for (int nt = 0; nt < 4; nt++)
            #pragma unroll
            for (int q = 0; q < 4; q++) c[mt][nt][q] = 0.f;

    const int lrow  = lane & 15;
    const int lcolb = (lane >> 4) * 16;

    for (int kt = 0; kt < nk; kt++) {
        const int s0 = sbeg + kt*32;
        __syncthreads();
        // e tiles: 128 rows x 32 s
        #pragma unroll
        for (int i = tid; i < 512; i += 256) {
            int r = i >> 2, c8 = (i & 3) * 8;
            size_t go = (size_t)(row0 + r)*Tn + s0 + c8;
            *(uint4*)&seh[r*ESTR + c8] = *(const uint4*)&g_ehi[go];
            *(uint4*)&sel[r*ESTR + c8] = *(const uint4*)&g_elo[go];
        }
        // V tiles: 32 s x 64 d
        {
            int r = tid >> 3, c8 = (tid & 7) * 8;
            size_t go = (size_t)(b*Tn + s0 + r)*HDn + c8;
            *(uint4*)&svh[r*VSTR + c8] = *(const uint4*)&g_vhi[go];
            *(uint4*)&svl[r*VSTR + c8] = *(const uint4*)&g_vlo[go];
        }
        __syncthreads();
        #pragma unroll
        for (int ks = 0; ks < 2; ks++) {
            uint32_t ah[2][4], al[2][4];
            #pragma unroll
            for (int mt = 0; mt < 2; mt++) {
                uint32_t base = (wm*32 + mt*16 + lrow)*(ESTR*2) + ks*32 + lcolb;
                ldsm4(ah[mt], sb_eh + base);
                ldsm4(al[mt], sb_el + base);
            }
            uint32_t bh[2][4], bl[2][4];
            #pragma unroll
            for (int ng = 0; ng < 2; ng++) {
                uint32_t base = (ks*16 + lrow)*(VSTR*2) + (wn*32 + ng*16)*2 + lcolb;
                ldsm4t(bh[ng], sb_vh + base);
                ldsm4t(bl[ng], sb_vl + base);
            }
            #pragma unroll
            for (int mt = 0; mt < 2; mt++) {
                #pragma unroll
                for (int ng = 0; ng < 2; ng++) {
                    float* c0 = c[mt][ng*2+0];
                    float* c1 = c[mt][ng*2+1];
                    mma16816(c0, ah[mt], bh[ng][0], bh[ng][1]);
                    mma16816(c1, ah[mt], bh[ng][2], bh[ng][3]);
                    mma16816(c0, ah[mt], bl[ng][0], bl[ng][1]);
                    mma16816(c1, ah[mt], bl[ng][2], bl[ng][3]);
                    mma16816(c0, al[mt], bh[ng][0], bh[ng][1]);
                    mma16816(c1, al[mt], bh[ng][2], bh[ng][3]);
                }
            }
        }
    }

    float* dst = &g_part[((size_t)chunk*NROWS + row0)*HDn];
    #pragma unroll
    for (int mt = 0; mt < 2; mt++) {
        #pragma unroll
        for (int nt = 0; nt < 4; nt++) {
            int r   = wm*32 + mt*16 + (lane >> 2);
            int col = wn*32 + nt*8 + (lane & 3)*2;
            *(float2*)&dst[(size_t)r*HDn + col]     = make_float2(c[mt][nt][0], c[mt][nt][1]);
            *(float2*)&dst[(size_t)(r+8)*HDn + col] = make_float2(c[mt][nt][2], c[mt][nt][3]);
        }
    }
}

// ---------------------------------------------------------------------------
// Kernel B4: finalize.
// ---------------------------------------------------------------------------
__global__ __launch_bounds__(256) void fin_kernel(float* __restrict__ out)
{
    const int idx = blockIdx.x * 256 + threadIdx.x;
    const int row = idx >> 4;
    const int d4  = (idx & 15) * 4;
    const int nch = (((row & (Tn-1)) | 127) / CHUNK) + 1;

    float4 s = make_float4(0.f, 0.f, 0.f, 0.f);
    for (int c = 0; c < nch; c++) {
        float4 p = *(const float4*)&g_part[((size_t)c*NROWS + row)*HDn + d4];
        s.x += p.x; s.y += p.y; s.z += p.z; s.w += p.w;
    }
    const float inv = g_iden[row];
    s.x *= inv; s.y *= inv; s.z *= inv; s.w *= inv;
    *(float4*)&out[(size_t)row*HDn + d4] = s;
}

// ---------------------------------------------------------------------------
extern "C" void kernel_launch(void* const* d_in, const int* in_sizes, int n_in,
                              void* d_out, int out_size)
{
    const float* x  = (const float*)d_in[0];
    const float* Wq = (const float*)d_in[1];
    const float* Wk = (const float*)d_in[2];
    const float* Wv = (const float*)d_in[3];
    float* out = (float*)d_out;

    cudaFuncSetAttribute(scores_mma, cudaFuncAttributeMaxDynamicSharedMemorySize, SC_SMEM);

    prep_x<<<(NROWS*Cn/8)/256, 256>>>(x);
    prep_w<<<(Cn*192/8 + 255)/256, 256>>>(Wq, Wk, Wv);
    qkv_mma<<<dim3(2, NROWS/64), 256>>>();
    scores_mma<<<dim3(Tn/128, NROWS/128), 256, SC_SMEM>>>();
    stats_kernel<<<NROWS/8, 256>>>();
    outp_mma<<<dim3(NCHUNK, NROWS/128), 256>>>();
    fin_kernel<<<(NROWS*HDn/4)/256, 256>>>(out);
}